// round 3
// baseline (speedup 1.0000x reference)
#include <cuda_runtime.h>

// Shape fixed by dataset: B=16, T=8192, N=32, depth=31.
constexpr int N_STACK = 32;
constexpr int DEPTH   = 31;
constexpr int OPSROW  = DEPTH * 5;        // 155 floats per (b,t)
constexpr int TPB     = 128;
constexpr int CHUNK   = 4;                // steps per smem chunk
constexpr int NCHUNK  = 8;                // 7*4 + 3 = 31
constexpr int LAST_NS = DEPTH - (NCHUNK - 1) * CHUNK;   // 3
constexpr int ROWS    = 5 * CHUNK;        // 20 rows per full chunk
constexpr int PADW    = TPB + 1;          // 129: conflict-free on read
constexpr int BUF_FLOATS = ROWS * PADW;   // 2580

__device__ __forceinline__ float tanh10(float x) {   // 10*tanh(x/10)
    float r;
    asm("tanh.approx.f32 %0, %1;" : "=f"(r) : "f"(x * 0.1f));
    return r * 10.0f;
}

// Coalesced chunk load: 128 threads fetch 128 rows x NF floats at col c0.
template<int NF>
__device__ __forceinline__ void load_chunk(float* pf, const float* __restrict__ ops,
                                           int blockBase, int c0, int tid) {
#pragma unroll
    for (int it = 0; it < NF; it++) {
        int lin = it * TPB + tid;
        int t = lin / NF;                // compile-time divisor
        int j = lin - t * NF;
        pf[it] = __ldg(ops + (size_t)(blockBase + t) * OPSROW + c0 + j);
    }
}

template<int NF>
__device__ __forceinline__ void store_chunk(const float* pf, float* buf, int tid) {
#pragma unroll
    for (int it = 0; it < NF; it++) {
        int lin = it * TPB + tid;
        int t = lin / NF;
        int j = lin - t * NF;
        buf[j * PADW + t] = pf[it];
    }
}

__global__ __launch_bounds__(TPB, 6)
void stack_machine_kernel(const float* __restrict__ sgn,
                          const float* __restrict__ logm,
                          const float* __restrict__ ops,
                          float* __restrict__ out,
                          int bt_total) {
    __shared__ float OPSB[2][BUF_FLOATS];
    const int tid = threadIdx.x;
    const int blockBase = blockIdx.x * TPB;
    const int bt = blockBase + tid;

    // ---- logm: direct float4 loads (row is 128B-aligned contiguous) ----
    float l[N_STACK];
    {
        const float4* Lv = reinterpret_cast<const float4*>(logm + (size_t)bt * N_STACK);
#pragma unroll
        for (int i = 0; i < N_STACK / 4; i++) {
            float4 v = __ldg(Lv + i);
            l[4 * i + 0] = v.x; l[4 * i + 1] = v.y;
            l[4 * i + 2] = v.z; l[4 * i + 3] = v.w;
        }
    }
    // ---- signs: original values are +/-1 -> pack to a bitmask (1 = negative) ----
    unsigned smask = 0;
    {
        const float4* Sv = reinterpret_cast<const float4*>(sgn + (size_t)bt * N_STACK);
#pragma unroll
        for (int i = 0; i < N_STACK / 4; i++) {
            float4 v = __ldg(Sv + i);
            smask |= (v.x < 0.0f ? 1u : 0u) << (4 * i + 0);
            smask |= (v.y < 0.0f ? 1u : 0u) << (4 * i + 1);
            smask |= (v.z < 0.0f ? 1u : 0u) << (4 * i + 2);
            smask |= (v.w < 0.0f ? 1u : 0u) << (4 * i + 3);
        }
    }

    // Running suffix sum-of-squares of the ORIGINAL logs. At step k, prev_logs
    // are original indices 0..30-k (step j writes index 30-j, which is consumed
    // as `top` at step j+1 and never re-read by the RMS slice afterwards).
    float SS = 0.0f;
#pragma unroll
    for (int i = 0; i < N_STACK - 1; i++) SS = fmaf(l[i], l[i], SS);

    float rs = (smask >> (N_STACK - 1)) & 1 ? -1.0f : 1.0f;  // running top sign
    float rl = l[N_STACK - 1];                               // running top log

    // ---- software-pipelined ops staging ----
    float pf[ROWS];
    load_chunk<ROWS>(pf, ops, blockBase, 0, tid);
    store_chunk<ROWS>(pf, OPSB[0], tid);
    __syncthreads();

#pragma unroll
    for (int ch = 0; ch < NCHUNK; ch++) {
        const int NS = (ch < NCHUNK - 1) ? CHUNK : LAST_NS;

        // Prefetch next chunk into registers (latency hidden under compute).
        if (ch + 1 < NCHUNK) {
            if (ch + 1 < NCHUNK - 1)
                load_chunk<ROWS>(pf, ops, blockBase, (ch + 1) * ROWS, tid);
            else
                load_chunk<5 * LAST_NS>(pf, ops, blockBase, (ch + 1) * ROWS, tid);
        }

        const float* B = OPSB[ch & 1];
#pragma unroll
        for (int kk = 0; kk < NS; kk++) {
            const int k  = ch * CHUNK + kk;
            const int si = N_STACK - 2 - k;          // sec = original input
            float ss = (smask >> si) & 1 ? -1.0f : 1.0f;
            float sl = l[si];

            float p0 = B[(kk * 5 + 0) * PADW + tid];
            float p1 = B[(kk * 5 + 1) * PADW + tid];
            float p2 = B[(kk * 5 + 2) * PADW + tid];
            float p3 = B[(kk * 5 + 3) * PADW + tid];
            float p4 = B[(kk * 5 + 4) * PADW + tid];

            // shared magnitude math for add & sub (signs don't change the logs)
            float mx = fmaxf(sl, rl), mn = fminf(sl, rl);
            float ed  = __expf(mn - mx);                 // e^{mn-mx} in (0,1]
            float lse = mx + __logf(1.0f + ed);
            float C1  = tanh10(tanh10(lse));             // same-sign (double clip, as ref)
            // exp(clip(d,-10,-.001)) == clip(exp(d)) since exp is monotone
            float edc  = fminf(fmaxf(ed, 4.5399930e-5f), 0.99900050f);
            float diff = __logf(1.0f - edc);
            bool  zr   = (mn == mx);
            float C2   = zr ? 0.0f : tanh10(mx + diff);  // opposite-sign

            bool  bx   = (sl >= rl);
            float srs  = ss * rs;
            bool  same = (srs > 0.0f);
            float bsA  = bx ? ss : rs;                   // big sign, y = +rs
            float bsS  = bx ? ss : -rs;                  // big sign, y = -rs

            float aS, aL, sS, sL;
            if (same) { aS = ss;               aL = C1;  sS = zr ? 0.0f : bsS;  sL = C2; }
            else      { aS = zr ? 0.0f : bsA;  aL = C2;  sS = ss;               sL = C1; }

            float mulL = tanh10(sl + rl);
            float divL = tanh10(sl - rl);

            float nsgn = aS * p0 + sS * p1 + srs * (p2 + p3) + ss * p4;
            float nlog = aL * p0 + sL * p1 + mulL * p2 + divL * p3 + sl * p4;

            // RMS rescale over [orig prefix (len 31-k), nlog]
            const float cs_inv = 1.0f / (float)(N_STACK - k);
            float msq   = fmaf(nlog, nlog, SS) * cs_inv + 1e-6f;
            float scale = fminf(10.0f * rsqrtf(msq), 1.0f);

            rl = nlog * scale;
            rs = nsgn;
            SS = fmaf(-sl, sl, SS);                      // drop sec from prefix
        }

        if (ch + 1 < NCHUNK) {
            if (ch + 1 < NCHUNK - 1)
                store_chunk<ROWS>(pf, OPSB[(ch + 1) & 1], tid);
            else
                store_chunk<5 * LAST_NS>(pf, OPSB[(ch + 1) & 1], tid);
            __syncthreads();
        }
    }

    out[bt]            = rs;   // (sign, log) stacked -> (2, B*T)
    out[bt_total + bt] = rl;
}

extern "C" void kernel_launch(void* const* d_in, const int* in_sizes, int n_in,
                              void* d_out, int out_size) {
    const float* sgn  = (const float*)d_in[0];
    const float* logm = (const float*)d_in[1];
    const float* ops  = (const float*)d_in[2];
    float* out = (float*)d_out;

    int bt_total = out_size / 2;
    int blocks = (bt_total + TPB - 1) / TPB;
    stack_machine_kernel<<<blocks, TPB>>>(sgn, logm, ops, out, bt_total);
}

// round 4
// speedup vs baseline: 1.2831x; 1.2831x over previous
#include <cuda_runtime.h>
#include <cstdint>

// Shape fixed by dataset: B=16, T=8192, N=32, depth=31.
constexpr int N_STACK = 32;
constexpr int DEPTH   = 31;
constexpr int OPSROW  = DEPTH * 5;   // 155 floats per (b,t) — ODD: stride-155/55/45 reads are bank-conflict-free
constexpr int TPB     = 128;

// Chunking of the 31 steps: 11 + 11 + 9 steps -> 55, 55, 45 floats per thread (all odd).
constexpr int BUF_FLOATS = 55 * TPB;              // largest chunk
__device__ __forceinline__ uint32_t smem_u32(const void* p) {
    return (uint32_t)__cvta_generic_to_shared(p);
}
__device__ __forceinline__ void cp_async4(uint32_t dst, const float* src) {
    asm volatile("cp.async.ca.shared.global [%0], [%1], 4;" :: "r"(dst), "l"(src));
}
__device__ __forceinline__ void cp_commit() { asm volatile("cp.async.commit_group;"); }
__device__ __forceinline__ void cp_wait0()  { asm volatile("cp.async.wait_group 0;" ::: "memory"); }

__device__ __forceinline__ float tanh10(float x) {   // 10*tanh(x/10)
    float r;
    asm("tanh.approx.f32 %0, %1;" : "=f"(r) : "f"(x * 0.1f));
    return r * 10.0f;
}

// Flat coalesced chunk load via cp.async: smem[idx] = g[idx + t*(155-LC)], t = idx/LC.
template<int LC>
__device__ __forceinline__ void load_chunk(float* buf, const float* __restrict__ g, int tid) {
    uint32_t base = smem_u32(buf);
#pragma unroll
    for (int it = 0; it < LC; it++) {
        int idx = it * TPB + tid;
        int t = idx / LC;                       // compile-time divisor -> mul/shift
        cp_async4(base + (uint32_t)idx * 4u, g + idx + t * (OPSROW - LC));
    }
    cp_commit();
}

struct State { float rs, rl, SS; };

// Compute NS steps starting at K0; thread's chunk row is buf[tid*LC ...] (odd LC -> conflict-free).
template<int LC, int NS, int K0>
__device__ __forceinline__ void compute_chunk(const float* buf, const float* l,
                                              unsigned smask, State& st, int tid) {
    const float* row = buf + tid * LC;
#pragma unroll
    for (int kk = 0; kk < NS; kk++) {
        const int k  = K0 + kk;
        const int si = N_STACK - 2 - k;                  // sec = original input
        float ss = (smask >> si) & 1 ? -1.0f : 1.0f;
        float sl = l[si];

        float p0 = row[kk * 5 + 0];
        float p1 = row[kk * 5 + 1];
        float p2 = row[kk * 5 + 2];
        float p3 = row[kk * 5 + 3];
        float p4 = row[kk * 5 + 4];

        float rs = st.rs, rl = st.rl;

        // shared magnitude math for add & sub (signs don't change the logs)
        float mx = fmaxf(sl, rl), mn = fminf(sl, rl);
        float ed  = __expf(mn - mx);                     // e^{mn-mx} in (0,1]
        float lse = mx + __logf(1.0f + ed);
        float C1  = tanh10(tanh10(lse));                 // same-sign (double clip, as ref)
        // exp(clip(d,-10,-.001)) == clip(exp(d)) (exp monotone)
        float edc  = fminf(fmaxf(ed, 4.5399930e-5f), 0.99900050f);
        float diff = __logf(1.0f - edc);
        bool  zr   = (mn == mx);
        float C2   = zr ? 0.0f : tanh10(mx + diff);      // opposite-sign

        bool  bx   = (sl >= rl);
        float srs  = ss * rs;
        bool  same = (srs > 0.0f);
        float bsA  = bx ? ss : rs;                       // big sign, y = +rs
        float bsS  = bx ? ss : -rs;                      // big sign, y = -rs

        float aS, aL, sS, sL;
        if (same) { aS = ss;               aL = C1;  sS = zr ? 0.0f : bsS;  sL = C2; }
        else      { aS = zr ? 0.0f : bsA;  aL = C2;  sS = ss;               sL = C1; }

        // Rare exact-zero-sign cases — bit-match reference.
        if (ss == 0.0f || rs == 0.0f) {
            if (ss != 0.0f)      { aS = ss;   aL = tanh10(sl); sS = ss;   sL = aL; }
            else if (rs != 0.0f) { aS = rs;   aL = tanh10(rl); sS = -rs;  sL = aL; }
            else                 { aS = 0.0f; aL = 0.0f;       sS = 0.0f; sL = 0.0f; }
        }

        float mulL = tanh10(sl + rl);
        float divL = tanh10(sl - rl);

        float nsgn = aS * p0 + sS * p1 + srs * (p2 + p3) + ss * p4;
        float nlog = aL * p0 + sL * p1 + mulL * p2 + divL * p3 + sl * p4;

        // RMS rescale over [orig prefix (len 31-k), nlog]
        const float cs_inv = 1.0f / (float)(N_STACK - k);
        float msq   = fmaf(nlog, nlog, st.SS) * cs_inv + 1e-6f;
        float scale = fminf(10.0f * rsqrtf(msq), 1.0f);

        st.rl = nlog * scale;
        st.rs = nsgn;
        st.SS = fmaf(-sl, sl, st.SS);                    // drop sec from prefix
    }
}

__global__ __launch_bounds__(TPB, 6)
void stack_machine_kernel(const float* __restrict__ sgn,
                          const float* __restrict__ logm,
                          const float* __restrict__ ops,
                          float* __restrict__ out,
                          int bt_total) {
    __shared__ float SM[BUF_FLOATS];
    const int tid = threadIdx.x;
    const int blockBase = blockIdx.x * TPB;
    const int bt = blockBase + tid;
    const float* gops = ops + (size_t)blockBase * OPSROW;

    // Kick off chunk 0 load immediately (overlaps logm/sgn loads + SS prefix).
    load_chunk<55>(SM, gops, tid);

    // logm: per-thread float4 loads (row = exactly one 128B line -> full-line use).
    float l[N_STACK];
    {
        const float4* Lv = reinterpret_cast<const float4*>(logm + (size_t)bt * N_STACK);
#pragma unroll
        for (int i = 0; i < N_STACK / 4; i++) {
            float4 v = __ldg(Lv + i);
            l[4 * i + 0] = v.x; l[4 * i + 1] = v.y;
            l[4 * i + 2] = v.z; l[4 * i + 3] = v.w;
        }
    }
    // signs are +/-1 -> pack into a bitmask (1 = negative)
    unsigned smask = 0;
    {
        const float4* Sv = reinterpret_cast<const float4*>(sgn + (size_t)bt * N_STACK);
#pragma unroll
        for (int i = 0; i < N_STACK / 4; i++) {
            float4 v = __ldg(Sv + i);
            smask |= (v.x < 0.0f ? 1u : 0u) << (4 * i + 0);
            smask |= (v.y < 0.0f ? 1u : 0u) << (4 * i + 1);
            smask |= (v.z < 0.0f ? 1u : 0u) << (4 * i + 2);
            smask |= (v.w < 0.0f ? 1u : 0u) << (4 * i + 3);
        }
    }

    // Running suffix sum-of-squares of the ORIGINAL logs (step j writes index
    // 30-j which is consumed as `top` at step j+1 and never re-read by RMS).
    State st;
    st.SS = 0.0f;
#pragma unroll
    for (int i = 0; i < N_STACK - 1; i++) st.SS = fmaf(l[i], l[i], st.SS);
    st.rs = (smask >> (N_STACK - 1)) & 1 ? -1.0f : 1.0f;
    st.rl = l[N_STACK - 1];

    // chunk 0: steps 0..10
    cp_wait0(); __syncthreads();
    compute_chunk<55, 11, 0>(SM, l, smask, st, tid);
    __syncthreads();

    // chunk 1: steps 11..21
    load_chunk<55>(SM, gops + 55, tid);
    cp_wait0(); __syncthreads();
    compute_chunk<55, 11, 11>(SM, l, smask, st, tid);
    __syncthreads();

    // chunk 2: steps 22..30
    load_chunk<45>(SM, gops + 110, tid);
    cp_wait0(); __syncthreads();
    compute_chunk<45, 9, 22>(SM, l, smask, st, tid);

    out[bt]            = st.rs;   // (sign, log) stacked -> (2, B*T)
    out[bt_total + bt] = st.rl;
}

extern "C" void kernel_launch(void* const* d_in, const int* in_sizes, int n_in,
                              void* d_out, int out_size) {
    const float* sgn  = (const float*)d_in[0];
    const float* logm = (const float*)d_in[1];
    const float* ops  = (const float*)d_in[2];
    float* out = (float*)d_out;

    int bt_total = out_size / 2;
    int blocks = (bt_total + TPB - 1) / TPB;
    stack_machine_kernel<<<blocks, TPB>>>(sgn, logm, ops, out, bt_total);
}

// round 5
// speedup vs baseline: 3.0674x; 2.3907x over previous
#include <cuda_runtime.h>
#include <cstdint>

// Shape fixed by dataset: B=16, T=8192, N=32, depth=31.
constexpr int N_STACK = 32;
constexpr int DEPTH   = 31;
constexpr int OPSROW  = DEPTH * 5;   // 155 floats per (b,t) row
constexpr int TPB     = 128;
constexpr int LPAD    = 33;          // per-thread smem log row stride (conflict-free)

__constant__ float CS_INV[DEPTH] = {
    1.0f/32, 1.0f/31, 1.0f/30, 1.0f/29, 1.0f/28, 1.0f/27, 1.0f/26, 1.0f/25,
    1.0f/24, 1.0f/23, 1.0f/22, 1.0f/21, 1.0f/20, 1.0f/19, 1.0f/18, 1.0f/17,
    1.0f/16, 1.0f/15, 1.0f/14, 1.0f/13, 1.0f/12, 1.0f/11, 1.0f/10, 1.0f/9,
    1.0f/8,  1.0f/7,  1.0f/6,  1.0f/5,  1.0f/4,  1.0f/3,  1.0f/2 };

__device__ __forceinline__ float tanh10(float x) {   // 10*tanh(x/10)
    float r;
    asm("tanh.approx.f32 %0, %1;" : "=f"(r) : "f"(x * 0.1f));
    return r * 10.0f;
}

struct State { float rs, rl, SS; };

// One soft-op step. sec = original stack entry (sl, ss=+/-1); top = running (st.rs, st.rl).
__device__ __forceinline__ void do_step(int k, const float* lrow, unsigned smask,
                                        float p0, float p1, float p2, float p3, float p4,
                                        State& st) {
    int   si = 30 - k;
    float sl = lrow[si];                                   // LDS, bank-conflict-free
    float ss = (smask >> si) & 1u ? -1.0f : 1.0f;
    float rs = st.rs, rl = st.rl;

    // shared magnitude math for add & sub (signs don't change the log values)
    float mx  = fmaxf(sl, rl), mn = fminf(sl, rl);
    float ed  = __expf(mn - mx);                           // e^{mn-mx} in (0,1]
    float lse = mx + __logf(1.0f + ed);
    float C1  = tanh10(tanh10(lse));                       // same-sign: double clip (as ref)
    // exp(clip(d,-10,-.001)) == clip(exp(d), e^-10, e^-.001)  (exp monotone)
    float edc  = fminf(fmaxf(ed, 4.5399930e-5f), 0.99900050f);
    float diff = __logf(1.0f - edc);
    bool  zr   = (mn == mx);
    float C2   = zr ? 0.0f : tanh10(mx + diff);            // opposite-sign: single clip

    bool  bx   = (sl >= rl);
    float srs  = ss * rs;
    bool  same = (srs > 0.0f);
    float bsA  = bx ? ss : rs;                             // big sign when y = +rs
    float bsS  = bx ? ss : -rs;                            // big sign when y = -rs

    float aS, aL, sS, sL;
    if (same) { aS = ss;               aL = C1;  sS = zr ? 0.0f : bsS;  sL = C2; }
    else      { aS = zr ? 0.0f : bsA;  aL = C2;  sS = ss;               sL = C1; }
    // ss is exactly +/-1 (original sign); only rs can be zero (only_x case)
    if (rs == 0.0f) { aS = ss; aL = tanh10(sl); sS = ss; sL = aL; }

    float mulL = tanh10(sl + rl);
    float divL = tanh10(sl - rl);

    float nsgn = aS * p0 + sS * p1 + srs * (p2 + p3) + ss * p4;
    float nlog = aL * p0 + sL * p1 + mulL * p2 + divL * p3 + sl * p4;

    // RMS rescale over [original prefix of len 31-k, nlog]
    float msq   = fmaf(nlog, nlog, st.SS) * CS_INV[k] + 1e-6f;
    float scale = fminf(10.0f * rsqrtf(msq), 1.0f);

    st.rl = nlog * scale;
    st.rs = nsgn;
    st.SS = fmaf(-sl, sl, st.SS);                          // drop sec from prefix
}

// O = number of leading floats in the first aligned 16B vector that belong to
// the previous row (alignment phase of this thread's 620-byte ops row).
template<int O>
__device__ __forceinline__ void run(int bt, int bt_total,
                                    const float* __restrict__ sgn,
                                    const float* __restrict__ logm,
                                    const float* __restrict__ ops,
                                    float* __restrict__ out,
                                    float* lrow) {
    // ---- logs: one 128B line per thread; square-sum + stash in smem row ----
    const float4* Lv = reinterpret_cast<const float4*>(logm + (size_t)bt * N_STACK);
    const float4* Sv = reinterpret_cast<const float4*>(sgn  + (size_t)bt * N_STACK);
    State st; st.SS = 0.0f;
    unsigned smask = 0;
#pragma unroll
    for (int i = 0; i < 8; i++) {
        float4 v = __ldg(Lv + i);
        lrow[4 * i + 0] = v.x; lrow[4 * i + 1] = v.y;
        lrow[4 * i + 2] = v.z; lrow[4 * i + 3] = v.w;
        st.SS = fmaf(v.x, v.x, st.SS);
        st.SS = fmaf(v.y, v.y, st.SS);
        st.SS = fmaf(v.z, v.z, st.SS);
        if (i < 7) st.SS = fmaf(v.w, v.w, st.SS);  // SS covers indices 0..30 only
        else       st.rl = v.w;                    // initial top log

        float4 s = __ldg(Sv + i);
        smask |= (s.x < 0.0f ? 1u : 0u) << (4 * i + 0);
        smask |= (s.y < 0.0f ? 1u : 0u) << (4 * i + 1);
        smask |= (s.z < 0.0f ? 1u : 0u) << (4 * i + 2);
        smask |= (s.w < 0.0f ? 1u : 0u) << (4 * i + 3);
    }
    st.rs = (smask >> 31) & 1u ? -1.0f : 1.0f;

    // ---- ops: vectorized stream with compile-time alignment phase O ----
    const float4* vp = reinterpret_cast<const float4*>(ops + (size_t)bt * OPSROW - O);
    float4 carry = make_float4(0.f, 0.f, 0.f, 0.f);
    if (O > 0) { carry = __ldg(vp); vp++; }

#pragma unroll 1
    for (int g = 0; g < 7; g++) {                          // 7 groups x 4 steps
        float4 v0 = __ldg(vp + 0), v1 = __ldg(vp + 1), v2 = __ldg(vp + 2),
               v3 = __ldg(vp + 3), v4 = __ldg(vp + 4);
        vp += 5;
        float f[24];
        if (O > 0) {
            f[0] = carry.x; f[1] = carry.y; f[2] = carry.z; f[3] = carry.w;
            f[4]  = v0.x; f[5]  = v0.y; f[6]  = v0.z; f[7]  = v0.w;
            f[8]  = v1.x; f[9]  = v1.y; f[10] = v1.z; f[11] = v1.w;
            f[12] = v2.x; f[13] = v2.y; f[14] = v2.z; f[15] = v2.w;
            f[16] = v3.x; f[17] = v3.y; f[18] = v3.z; f[19] = v3.w;
            f[20] = v4.x; f[21] = v4.y; f[22] = v4.z; f[23] = v4.w;
            carry = v4;
        } else {
            f[0]  = v0.x; f[1]  = v0.y; f[2]  = v0.z; f[3]  = v0.w;
            f[4]  = v1.x; f[5]  = v1.y; f[6]  = v1.z; f[7]  = v1.w;
            f[8]  = v2.x; f[9]  = v2.y; f[10] = v2.z; f[11] = v2.w;
            f[12] = v3.x; f[13] = v3.y; f[14] = v3.z; f[15] = v3.w;
            f[16] = v4.x; f[17] = v4.y; f[18] = v4.z; f[19] = v4.w;
            f[20] = f[21] = f[22] = f[23] = 0.0f;
        }
        int k0 = 4 * g;
#pragma unroll
        for (int kk = 0; kk < 4; kk++)
            do_step(k0 + kk, lrow, smask,
                    f[O + 5 * kk + 0], f[O + 5 * kk + 1], f[O + 5 * kk + 2],
                    f[O + 5 * kk + 3], f[O + 5 * kk + 4], st);
    }

    // ---- epilogue: steps 28..30 (row floats 140..154) ----
    {
        float f[20];
#pragma unroll
        for (int i = 0; i < 20; i++) f[i] = 0.0f;
        if (O == 0) {
            float4 v0 = __ldg(vp + 0), v1 = __ldg(vp + 1), v2 = __ldg(vp + 2), v3 = __ldg(vp + 3);
            f[0]  = v0.x; f[1]  = v0.y; f[2]  = v0.z; f[3]  = v0.w;
            f[4]  = v1.x; f[5]  = v1.y; f[6]  = v1.z; f[7]  = v1.w;
            f[8]  = v2.x; f[9]  = v2.y; f[10] = v2.z; f[11] = v2.w;
            f[12] = v3.x; f[13] = v3.y; f[14] = v3.z;
        } else if (O == 1) {
            float4 v0 = __ldg(vp + 0), v1 = __ldg(vp + 1), v2 = __ldg(vp + 2);
            f[0] = carry.x; f[1] = carry.y; f[2] = carry.z; f[3] = carry.w;
            f[4]  = v0.x; f[5]  = v0.y; f[6]  = v0.z; f[7]  = v0.w;
            f[8]  = v1.x; f[9]  = v1.y; f[10] = v1.z; f[11] = v1.w;
            f[12] = v2.x; f[13] = v2.y; f[14] = v2.z; f[15] = v2.w;
        } else {  // O == 2 or 3 (overreads stay inside the ops array: last row has O==1)
            float4 v0 = __ldg(vp + 0), v1 = __ldg(vp + 1), v2 = __ldg(vp + 2), v3 = __ldg(vp + 3);
            f[0] = carry.x; f[1] = carry.y; f[2] = carry.z; f[3] = carry.w;
            f[4]  = v0.x; f[5]  = v0.y; f[6]  = v0.z; f[7]  = v0.w;
            f[8]  = v1.x; f[9]  = v1.y; f[10] = v1.z; f[11] = v1.w;
            f[12] = v2.x; f[13] = v2.y; f[14] = v2.z; f[15] = v2.w;
            f[16] = v3.x; f[17] = v3.y; f[18] = v3.z; f[19] = v3.w;
        }
#pragma unroll
        for (int kk = 0; kk < 3; kk++)
            do_step(28 + kk, lrow, smask,
                    f[O + 5 * kk + 0], f[O + 5 * kk + 1], f[O + 5 * kk + 2],
                    f[O + 5 * kk + 3], f[O + 5 * kk + 4], st);
    }

    out[bt]            = st.rs;   // (sign, log) stacked -> (2, B*T)
    out[bt_total + bt] = st.rl;
}

__global__ __launch_bounds__(TPB, 6)
void stack_machine_kernel(const float* __restrict__ sgn,
                          const float* __restrict__ logm,
                          const float* __restrict__ ops,
                          float* __restrict__ out,
                          int bt_total) {
    __shared__ float LBUF[TPB * LPAD];
    const int tid = threadIdx.x;
    const int c   = blockIdx.x & 3;                       // alignment class (bt mod 4)
    const int bt  = 4 * ((blockIdx.x >> 2) * TPB + tid) + c;
    float* lrow = LBUF + tid * LPAD;

    // O = (4 - c) & 3 : floats of the previous row in the first aligned vector.
    if      (c == 0) run<0>(bt, bt_total, sgn, logm, ops, out, lrow);
    else if (c == 1) run<3>(bt, bt_total, sgn, logm, ops, out, lrow);
    else if (c == 2) run<2>(bt, bt_total, sgn, logm, ops, out, lrow);
    else             run<1>(bt, bt_total, sgn, logm, ops, out, lrow);
}

extern "C" void kernel_launch(void* const* d_in, const int* in_sizes, int n_in,
                              void* d_out, int out_size) {
    const float* sgn  = (const float*)d_in[0];
    const float* logm = (const float*)d_in[1];
    const float* ops  = (const float*)d_in[2];
    float* out = (float*)d_out;

    int bt_total = out_size / 2;                 // 131072; divisible by 4*TPB
    int blocks = bt_total / TPB;
    stack_machine_kernel<<<blocks, TPB>>>(sgn, logm, ops, out, bt_total);
}